// round 1
// baseline (speedup 1.0000x reference)
#include <cuda_runtime.h>
#include <cuda_bf16.h>

// GRU: B=4096, T=512, I=32, H=32. One warp per batch row.
// Lane j owns gate rows (r_j, z_j, n_j); 6 weight rows (192 floats) live in registers.
// Per step: broadcast x_k/h_k via shuffles, 192 FFMAs on 4 accumulators, exp-based gates.

#define GRU_B 4096
#define GRU_T 512
#define GRU_I 32
#define GRU_H 32

__device__ __forceinline__ float sigmoid_fast(float v) {
    // 1/(1+e^-v): v->+inf: e->0 ->1; v->-inf: e->inf -> 0. No NaN.
    float e = __expf(-v);
    return __fdividef(1.0f, 1.0f + e);
}

__device__ __forceinline__ float tanh_fast(float v) {
    // tanh via |x| to avoid inf/inf: e = exp(-2|x|) in (0,1]
    float a = fabsf(v);
    float e = __expf(-2.0f * a);
    float t = __fdividef(1.0f - e, 1.0f + e);
    return copysignf(t, v);
}

__global__ void gru_warp_kernel(const float* __restrict__ x,
                                const float* __restrict__ W_ih,
                                const float* __restrict__ W_hh,
                                const float* __restrict__ b_ih,
                                const float* __restrict__ b_hh,
                                const float* __restrict__ w_head,
                                const float* __restrict__ b_head,
                                float* __restrict__ out) {
    const int warp = blockIdx.x;          // one block = one warp = one batch row
    const int j = threadIdx.x & 31;       // lane = gate index within each gate group

    const float* xb = x + (size_t)warp * (GRU_T * GRU_I);

    // Load weight rows j, 32+j, 64+j of W_ih and W_hh into registers (one-time, L2-shared).
    float wir[32], wiz[32], win[32], whr[32], whz[32], whn[32];
    const float* pir = W_ih + (size_t)j * 32;
    const float* piz = W_ih + (size_t)(32 + j) * 32;
    const float* pin = W_ih + (size_t)(64 + j) * 32;
    const float* phr = W_hh + (size_t)j * 32;
    const float* phz = W_hh + (size_t)(32 + j) * 32;
    const float* phn = W_hh + (size_t)(64 + j) * 32;
#pragma unroll
    for (int k = 0; k < 32; k++) {
        wir[k] = pir[k];
        wiz[k] = piz[k];
        win[k] = pin[k];
        whr[k] = phr[k];
        whz[k] = phz[k];
        whn[k] = phn[k];
    }

    const float br  = b_ih[j]      + b_hh[j];        // r bias (combined)
    const float bz  = b_ih[32 + j] + b_hh[32 + j];   // z bias (combined)
    const float bnx = b_ih[64 + j];                  // n: input-side bias
    const float bnh = b_hh[64 + j];                  // n: hidden-side bias (inside r*(...))

    float h = 0.0f;
    float xv = xb[j];  // x_t=0, lane j holds element j (coalesced 128B)

#pragma unroll 1
    for (int t = 0; t < GRU_T; t++) {
        // Prefetch next timestep's x (predicated; consumed ~1 full step later).
        float xnext = 0.0f;
        if (t + 1 < GRU_T) xnext = xb[(t + 1) * GRU_I + j];

        float accr = br, accz = bz, accnx = bnx, accnh = bnh;
#pragma unroll
        for (int k = 0; k < 32; k++) {
            float xk = __shfl_sync(0xffffffffu, xv, k);
            float hk = __shfl_sync(0xffffffffu, h, k);
            accr  = fmaf(xk, wir[k], accr);
            accz  = fmaf(xk, wiz[k], accz);
            accnx = fmaf(xk, win[k], accnx);
            accr  = fmaf(hk, whr[k], accr);
            accz  = fmaf(hk, whz[k], accz);
            accnh = fmaf(hk, whn[k], accnh);
        }

        float r = sigmoid_fast(accr);
        float z = sigmoid_fast(accz);
        float n = tanh_fast(fmaf(r, accnh, accnx));
        // h = (1-z)*n + z*h = n + z*(h-n)
        h = fmaf(z, h - n, n);
        xv = xnext;
    }

    // Head: y = sum_j h_j * w_head[j] + b_head
    float v = h * w_head[j];
#pragma unroll
    for (int off = 16; off > 0; off >>= 1)
        v += __shfl_xor_sync(0xffffffffu, v, off);

    if (j == 0) out[warp] = v + b_head[0];
}

extern "C" void kernel_launch(void* const* d_in, const int* in_sizes, int n_in,
                              void* d_out, int out_size) {
    const float* x      = (const float*)d_in[0];
    const float* W_ih   = (const float*)d_in[1];
    const float* W_hh   = (const float*)d_in[2];
    const float* b_ih   = (const float*)d_in[3];
    const float* b_hh   = (const float*)d_in[4];
    const float* w_head = (const float*)d_in[5];
    const float* b_head = (const float*)d_in[6];
    float* out = (float*)d_out;

    gru_warp_kernel<<<GRU_B, 32>>>(x, W_ih, W_hh, b_ih, b_hh, w_head, b_head, out);
}

// round 4
// speedup vs baseline: 2.1461x; 2.1461x over previous
#include <cuda_runtime.h>

// GRU: B=4096, T=512, I=H=32. One warp per batch row.
// - Packed fp32x2 FMAs (fma.rn.f32x2) along the contraction dim: 96 FFMA2/step.
// - h broadcast as 64-bit pairs: 1 shfl_xor + 16 pair-broadcasts (33 SHFL/step).
// - x streamed through smem with cp.async double buffering (16-step chunks).

#define GRU_B 4096
#define GRU_T 512
#define GRU_H 32
#define CHUNK 16
#define NCHUNK (GRU_T / CHUNK)
#define FULL 0xffffffffu

typedef unsigned long long u64;

__device__ __forceinline__ u64 ffma2(u64 a, u64 b, u64 c) {
    u64 d;
    asm("fma.rn.f32x2 %0, %1, %2, %3;" : "=l"(d) : "l"(a), "l"(b), "l"(c));
    return d;
}
__device__ __forceinline__ u64 pack2(float lo, float hi) {
    u64 r;
    asm("mov.b64 %0, {%1, %2};" : "=l"(r) : "f"(lo), "f"(hi));
    return r;
}
__device__ __forceinline__ float2 unpack2(u64 v) {
    float2 f;
    asm("mov.b64 {%0, %1}, %2;" : "=f"(f.x), "=f"(f.y) : "l"(v));
    return f;
}
__device__ __forceinline__ float sigmoid_fast(float v) {
    float e = __expf(-v);
    return __fdividef(1.0f, 1.0f + e);
}
__device__ __forceinline__ float tanh_fast(float v) {
    float a = fabsf(v);
    float e = __expf(-2.0f * a);
    float t = __fdividef(1.0f - e, 1.0f + e);
    return copysignf(t, v);
}

__global__ void __launch_bounds__(32) gru_warp_kernel(
        const float* __restrict__ x,
        const float* __restrict__ W_ih,
        const float* __restrict__ W_hh,
        const float* __restrict__ b_ih,
        const float* __restrict__ b_hh,
        const float* __restrict__ w_head,
        const float* __restrict__ b_head,
        float* __restrict__ out) {
    __shared__ __align__(16) float xsm[2][CHUNK * GRU_H];

    const int j = threadIdx.x;  // lane = gate-row index
    const float* xb = x + (size_t)blockIdx.x * (GRU_T * GRU_H);

    // Weight rows for lane j, stored as 16 packed float2 each (registers).
    u64 wir[16], wiz[16], win[16], whr[16], whz[16], whn[16];
    {
        const u64* a = (const u64*)(W_ih + (size_t)j * 32);
        const u64* b = (const u64*)(W_ih + (size_t)(32 + j) * 32);
        const u64* c = (const u64*)(W_ih + (size_t)(64 + j) * 32);
        const u64* d = (const u64*)(W_hh + (size_t)j * 32);
        const u64* e = (const u64*)(W_hh + (size_t)(32 + j) * 32);
        const u64* f = (const u64*)(W_hh + (size_t)(64 + j) * 32);
#pragma unroll
        for (int k = 0; k < 16; k++) {
            wir[k] = a[k]; wiz[k] = b[k]; win[k] = c[k];
            whr[k] = d[k]; whz[k] = e[k]; whn[k] = f[k];
        }
    }
    const float br  = b_ih[j] + b_hh[j];
    const float bz  = b_ih[32 + j] + b_hh[32 + j];
    const float bnx = b_ih[64 + j];
    const float bnh = b_hh[64 + j];
    const u64 ar0  = pack2(br, 0.0f);
    const u64 az0  = pack2(bz, 0.0f);
    const u64 anx0 = pack2(bnx, 0.0f);
    const u64 anh0 = pack2(bnh, 0.0f);

    const unsigned smem0 = (unsigned)__cvta_generic_to_shared(&xsm[0][0]);
    const unsigned smem1 = (unsigned)__cvta_generic_to_shared(&xsm[1][0]);

    // Prefetch chunks 0 and 1 (2048B each; each lane copies 4x16B).
#pragma unroll
    for (int i = 0; i < 4; i++) {
        unsigned dst = smem0 + i * 512 + j * 16;
        size_t src = __cvta_generic_to_global(xb + i * 128 + j * 4);
        asm volatile("cp.async.cg.shared.global [%0], [%1], 16;" :: "r"(dst), "l"(src) : "memory");
    }
    asm volatile("cp.async.commit_group;" ::: "memory");
#pragma unroll
    for (int i = 0; i < 4; i++) {
        unsigned dst = smem1 + i * 512 + j * 16;
        size_t src = __cvta_generic_to_global(xb + CHUNK * GRU_H + i * 128 + j * 4);
        asm volatile("cp.async.cg.shared.global [%0], [%1], 16;" :: "r"(dst), "l"(src) : "memory");
    }
    asm volatile("cp.async.commit_group;" ::: "memory");

    float h = 0.0f;

#pragma unroll 1
    for (int c = 0; c < NCHUNK; c++) {
        asm volatile("cp.async.wait_group 1;" ::: "memory");
        __syncwarp();
        const u64* xs = (const u64*)xsm[c & 1];

#pragma unroll 1
        for (int tl = 0; tl < CHUNK; tl++) {
            const ulonglong2* xq = (const ulonglong2*)(xs + tl * 16);
            // Form this lane's h-pair {h_2p, h_2p+1}, p = j>>1.
            float hq = __shfl_xor_sync(FULL, h, 1);
            u64 myPair = (j & 1) ? pack2(hq, h) : pack2(h, hq);

            u64 ar = ar0, az = az0, anx = anx0, anh = anh0;
#pragma unroll
            for (int q = 0; q < 8; q++) {
                ulonglong2 xx = xq[q];                       // x pairs 2q, 2q+1 (uniform LDS.128)
                u64 hp0 = __shfl_sync(FULL, myPair, 4 * q);      // h pair 2q   (src lane 4q)
                u64 hp1 = __shfl_sync(FULL, myPair, 4 * q + 2);  // h pair 2q+1 (src lane 4q+2)
                ar  = ffma2(xx.x, wir[2 * q], ar);
                az  = ffma2(xx.x, wiz[2 * q], az);
                anx = ffma2(xx.x, win[2 * q], anx);
                ar  = ffma2(hp0, whr[2 * q], ar);
                az  = ffma2(hp0, whz[2 * q], az);
                anh = ffma2(hp0, whn[2 * q], anh);
                ar  = ffma2(xx.y, wir[2 * q + 1], ar);
                az  = ffma2(xx.y, wiz[2 * q + 1], az);
                anx = ffma2(xx.y, win[2 * q + 1], anx);
                ar  = ffma2(hp1, whr[2 * q + 1], ar);
                az  = ffma2(hp1, whz[2 * q + 1], az);
                anh = ffma2(hp1, whn[2 * q + 1], anh);
            }
            float2 fr = unpack2(ar), fz = unpack2(az);
            float2 fnx = unpack2(anx), fnh = unpack2(anh);
            float r = sigmoid_fast(fr.x + fr.y);
            float z = sigmoid_fast(fz.x + fz.y);
            float n = tanh_fast(fmaf(r, fnh.x + fnh.y, fnx.x + fnx.y));
            h = fmaf(z, h - n, n);   // h = n + z*(h - n)
        }

        __syncwarp();  // all lanes done reading buf[c&1] before overwriting it
        if (c + 2 < NCHUNK) {
            unsigned dstb = (c & 1) ? smem1 : smem0;
            const float* srcb = xb + (size_t)(c + 2) * CHUNK * GRU_H;
#pragma unroll
            for (int i = 0; i < 4; i++) {
                unsigned dst = dstb + i * 512 + j * 16;
                size_t src = __cvta_generic_to_global(srcb + i * 128 + j * 4);
                asm volatile("cp.async.cg.shared.global [%0], [%1], 16;" :: "r"(dst), "l"(src) : "memory");
            }
        }
        asm volatile("cp.async.commit_group;" ::: "memory");  // one group per iter (may be empty)
    }

    // Head: y = sum_j h_j * w_head[j] + b_head
    float v = h * w_head[j];
#pragma unroll
    for (int off = 16; off > 0; off >>= 1)
        v += __shfl_xor_sync(FULL, v, off);
    if (j == 0) out[blockIdx.x] = v + b_head[0];
}

extern "C" void kernel_launch(void* const* d_in, const int* in_sizes, int n_in,
                              void* d_out, int out_size) {
    const float* x      = (const float*)d_in[0];
    const float* W_ih   = (const float*)d_in[1];
    const float* W_hh   = (const float*)d_in[2];
    const float* b_ih   = (const float*)d_in[3];
    const float* b_hh   = (const float*)d_in[4];
    const float* w_head = (const float*)d_in[5];
    const float* b_head = (const float*)d_in[6];
    float* out = (float*)d_out;

    gru_warp_kernel<<<GRU_B, 32>>>(x, W_ih, W_hh, b_ih, b_hh, w_head, b_head, out);
}

// round 6
// speedup vs baseline: 2.3282x; 1.0848x over previous
#include <cuda_runtime.h>

// GRU B=4096, T=512, I=H=32 — split into:
//  Kernel A: gx[b,t,{r,z,n},j] = x_t · W_ih^T + b_ih (+ b_hh folded for r,z)  [parallel GEMM]
//  Kernel B: h recurrence with h-side FMAs only (48 FFMA2/step), smem h-broadcast.

#define GRU_B 4096
#define GRU_T 512
#define GRU_H 32
#define WPB 4            // warps per block
#define ACHUNK 16        // kernel A: x chunk (timesteps per buffer)
#define BCHUNK 8         // kernel B: gx chunk (timesteps per buffer)
#define ANCH (GRU_T / ACHUNK)
#define BNCH (GRU_T / BCHUNK)
#define FULL 0xffffffffu

typedef unsigned long long u64;

// Scratch for gx: [B][T][3][32] fp32 = 805 MB (static device array; no runtime alloc).
__device__ float d_gx[(size_t)GRU_B * GRU_T * 96];

__device__ __forceinline__ u64 ffma2(u64 a, u64 b, u64 c) {
    u64 d;
    asm("fma.rn.f32x2 %0, %1, %2, %3;" : "=l"(d) : "l"(a), "l"(b), "l"(c));
    return d;
}
__device__ __forceinline__ u64 pack2(float lo, float hi) {
    u64 r;
    asm("mov.b64 %0, {%1, %2};" : "=l"(r) : "f"(lo), "f"(hi));
    return r;
}
__device__ __forceinline__ float2 unpack2(u64 v) {
    float2 f;
    asm("mov.b64 {%0, %1}, %2;" : "=f"(f.x), "=f"(f.y) : "l"(v));
    return f;
}
__device__ __forceinline__ float sigmoid_fast(float v) {
    float e = __expf(-v);
    return __fdividef(1.0f, 1.0f + e);
}
__device__ __forceinline__ float tanh_fast(float v) {
    float a = fabsf(v);
    float e = __expf(-2.0f * a);
    float t = __fdividef(1.0f - e, 1.0f + e);
    return copysignf(t, v);
}
__device__ __forceinline__ void cpasync16(unsigned dst, const float* src) {
    size_t s = __cvta_generic_to_global(src);
    asm volatile("cp.async.cg.shared.global [%0], [%1], 16;" :: "r"(dst), "l"(s) : "memory");
}

// ───────────────────────── Kernel A: gx precompute ─────────────────────────
__global__ void __launch_bounds__(128, 3) gru_gx_kernel(
        const float* __restrict__ x,
        const float* __restrict__ W_ih,
        const float* __restrict__ b_ih,
        const float* __restrict__ b_hh) {
    __shared__ __align__(16) float xsm[WPB][2][ACHUNK * GRU_H];

    const int w = threadIdx.x >> 5;
    const int j = threadIdx.x & 31;
    const int b = blockIdx.x * WPB + w;

    const float* xb = x + (size_t)b * (GRU_T * GRU_H);
    float* gxb = d_gx + (size_t)b * (GRU_T * 96);

    // W_ih rows j, 32+j, 64+j as packed float2 (48 u64 = 96 regs).
    u64 wir[16], wiz[16], win[16];
    {
        const u64* a = (const u64*)(W_ih + (size_t)j * 32);
        const u64* c = (const u64*)(W_ih + (size_t)(32 + j) * 32);
        const u64* d = (const u64*)(W_ih + (size_t)(64 + j) * 32);
#pragma unroll
        for (int k = 0; k < 16; k++) { wir[k] = a[k]; wiz[k] = c[k]; win[k] = d[k]; }
    }
    // Fold b_hh for r,z here (h-independent); n's hidden bias stays in kernel B.
    const u64 ar0 = pack2(b_ih[j] + b_hh[j], 0.0f);
    const u64 az0 = pack2(b_ih[32 + j] + b_hh[32 + j], 0.0f);
    const u64 an0 = pack2(b_ih[64 + j], 0.0f);

    const unsigned sm0 = (unsigned)__cvta_generic_to_shared(&xsm[w][0][0]);
    const unsigned sm1 = (unsigned)__cvta_generic_to_shared(&xsm[w][1][0]);

    // Prefetch chunks 0,1 (2048 B each; 4×16 B per lane).
#pragma unroll
    for (int i = 0; i < 4; i++) cpasync16(sm0 + i * 512 + j * 16, xb + i * 128 + j * 4);
    asm volatile("cp.async.commit_group;" ::: "memory");
#pragma unroll
    for (int i = 0; i < 4; i++)
        cpasync16(sm1 + i * 512 + j * 16, xb + ACHUNK * GRU_H + i * 128 + j * 4);
    asm volatile("cp.async.commit_group;" ::: "memory");

#pragma unroll 1
    for (int c = 0; c < ANCH; c++) {
        asm volatile("cp.async.wait_group 1;" ::: "memory");
        __syncwarp();
        const ulonglong2* xs = (const ulonglong2*)&xsm[w][c & 1][0];

#pragma unroll 1
        for (int tl = 0; tl < ACHUNK; tl++) {
            const ulonglong2* xq = xs + tl * 8;
            u64 ar = ar0, az = az0, an = an0;
#pragma unroll
            for (int q = 0; q < 8; q++) {
                ulonglong2 xx = xq[q];  // uniform broadcast LDS.128
                ar = ffma2(xx.x, wir[2 * q], ar);
                az = ffma2(xx.x, wiz[2 * q], az);
                an = ffma2(xx.x, win[2 * q], an);
                ar = ffma2(xx.y, wir[2 * q + 1], ar);
                az = ffma2(xx.y, wiz[2 * q + 1], az);
                an = ffma2(xx.y, win[2 * q + 1], an);
            }
            float2 fr = unpack2(ar), fz = unpack2(az), fn = unpack2(an);
            float* o = gxb + (size_t)(c * ACHUNK + tl) * 96;
            o[j]      = fr.x + fr.y;
            o[32 + j] = fz.x + fz.y;
            o[64 + j] = fn.x + fn.y;
        }

        __syncwarp();
        if (c + 2 < ANCH) {
            unsigned dst = (c & 1) ? sm1 : sm0;
            const float* src = xb + (size_t)(c + 2) * ACHUNK * GRU_H;
#pragma unroll
            for (int i = 0; i < 4; i++) cpasync16(dst + i * 512 + j * 16, src + i * 128 + j * 4);
        }
        asm volatile("cp.async.commit_group;" ::: "memory");
    }
}

// ───────────────────────── Kernel B: recurrence ─────────────────────────
__global__ void __launch_bounds__(128, 3) gru_rec_kernel(
        const float* __restrict__ W_hh,
        const float* __restrict__ b_hh,
        const float* __restrict__ w_head,
        const float* __restrict__ b_head,
        float* __restrict__ out) {
    __shared__ __align__(16) float gxsm[WPB][2][BCHUNK * 96];  // 24 KB
    __shared__ __align__(16) float hbuf[WPB][2][GRU_H];        // 1 KB

    const int w = threadIdx.x >> 5;
    const int j = threadIdx.x & 31;
    const int b = blockIdx.x * WPB + w;

    const float* gxb = d_gx + (size_t)b * (GRU_T * 96);

    // W_hh rows j, 32+j, 64+j packed (96 regs).
    u64 whr[16], whz[16], whn[16];
    {
        const u64* a = (const u64*)(W_hh + (size_t)j * 32);
        const u64* c = (const u64*)(W_hh + (size_t)(32 + j) * 32);
        const u64* d = (const u64*)(W_hh + (size_t)(64 + j) * 32);
#pragma unroll
        for (int k = 0; k < 16; k++) { whr[k] = a[k]; whz[k] = c[k]; whn[k] = d[k]; }
    }
    const u64 anh0 = pack2(b_hh[64 + j], 0.0f);  // n-gate hidden bias (inside r*(...))

    const unsigned gsm0 = (unsigned)__cvta_generic_to_shared(&gxsm[w][0][0]);
    const unsigned gsm1 = (unsigned)__cvta_generic_to_shared(&gxsm[w][1][0]);

    // h init
    hbuf[w][0][j] = 0.0f;
    float h = 0.0f;

    // Prefetch gx chunks 0,1 (3072 B each; 6×16 B per lane).
#pragma unroll
    for (int i = 0; i < 6; i++) cpasync16(gsm0 + i * 512 + j * 16, gxb + i * 128 + j * 4);
    asm volatile("cp.async.commit_group;" ::: "memory");
#pragma unroll
    for (int i = 0; i < 6; i++)
        cpasync16(gsm1 + i * 512 + j * 16, gxb + BCHUNK * 96 + i * 128 + j * 4);
    asm volatile("cp.async.commit_group;" ::: "memory");
    __syncwarp();

#pragma unroll 1
    for (int c = 0; c < BNCH; c++) {
        asm volatile("cp.async.wait_group 1;" ::: "memory");
        __syncwarp();
        const float* gs = &gxsm[w][c & 1][0];

#pragma unroll 1
        for (int tl = 0; tl < BCHUNK; tl++) {
            const int t = c * BCHUNK + tl;
            const ulonglong2* hq = (const ulonglong2*)&hbuf[w][t & 1][0];

            u64 ar = pack2(0.0f, 0.0f), az = pack2(0.0f, 0.0f), anh = anh0;
#pragma unroll
            for (int q = 0; q < 8; q++) {
                ulonglong2 hh = hq[q];  // uniform broadcast LDS.128 of h pairs
                ar  = ffma2(hh.x, whr[2 * q], ar);
                az  = ffma2(hh.x, whz[2 * q], az);
                anh = ffma2(hh.x, whn[2 * q], anh);
                ar  = ffma2(hh.y, whr[2 * q + 1], ar);
                az  = ffma2(hh.y, whz[2 * q + 1], az);
                anh = ffma2(hh.y, whn[2 * q + 1], anh);
            }
            float gxr = gs[tl * 96 + j];
            float gxz = gs[tl * 96 + 32 + j];
            float gxn = gs[tl * 96 + 64 + j];
            float2 fr = unpack2(ar), fz = unpack2(az), fnh = unpack2(anh);
            float r = sigmoid_fast(gxr + fr.x + fr.y);
            float z = sigmoid_fast(gxz + fz.x + fz.y);
            float n = tanh_fast(fmaf(r, fnh.x + fnh.y, gxn));
            h = fmaf(z, h - n, n);  // h = n + z*(h - n)

            hbuf[w][(t + 1) & 1][j] = h;
            __syncwarp();  // stores visible & all reads of hbuf[t&1] complete
        }

        if (c + 2 < BNCH) {
            unsigned dst = (c & 1) ? gsm1 : gsm0;
            const float* src = gxb + (size_t)(c + 2) * BCHUNK * 96;
#pragma unroll
            for (int i = 0; i < 6; i++) cpasync16(dst + i * 512 + j * 16, src + i * 128 + j * 4);
        }
        asm volatile("cp.async.commit_group;" ::: "memory");
    }

    // Head: y = sum_j h_j * w_head[j] + b_head
    float v = h * w_head[j];
#pragma unroll
    for (int off = 16; off > 0; off >>= 1)
        v += __shfl_xor_sync(FULL, v, off);
    if (j == 0) out[b] = v + b_head[0];
}

extern "C" void kernel_launch(void* const* d_in, const int* in_sizes, int n_in,
                              void* d_out, int out_size) {
    const float* x      = (const float*)d_in[0];
    const float* W_ih   = (const float*)d_in[1];
    const float* W_hh   = (const float*)d_in[2];
    const float* b_ih   = (const float*)d_in[3];
    const float* b_hh   = (const float*)d_in[4];
    const float* w_head = (const float*)d_in[5];
    const float* b_head = (const float*)d_in[6];
    float* out = (float*)d_out;

    gru_gx_kernel<<<GRU_B / WPB, 32 * WPB>>>(x, W_ih, b_ih, b_hh);
    gru_rec_kernel<<<GRU_B / WPB, 32 * WPB>>>(W_hh, b_hh, w_head, b_head, out);
}

// round 7
// speedup vs baseline: 2.3305x; 1.0010x over previous
#include <cuda_runtime.h>

// GRU B=4096, T=512, I=H=32 — two kernels:
//  A: gx[b,t,{r,z,n},j] = x_t · W_ih^T + biases (parallel GEMM, warp-per-row)
//  B: h recurrence, TWO rows per warp (shared W_hh registers, doubled ILP to
//     hide the serial chain), smem h-broadcast, cp.async gx streaming.

#define GRU_B 4096
#define GRU_T 512
#define GRU_H 32
#define WPB 4            // warps per block
#define ACHUNK 16        // kernel A: timesteps per x buffer
#define BCHUNK 4         // kernel B: timesteps per gx buffer
#define ANCH (GRU_T / ACHUNK)
#define BNCH (GRU_T / BCHUNK)
#define FULL 0xffffffffu

typedef unsigned long long u64;

// gx scratch: [B][T][3][32] fp32 = 805 MB (static device array; no runtime alloc).
__device__ float d_gx[(size_t)GRU_B * GRU_T * 96];

__device__ __forceinline__ u64 ffma2(u64 a, u64 b, u64 c) {
    u64 d;
    asm("fma.rn.f32x2 %0, %1, %2, %3;" : "=l"(d) : "l"(a), "l"(b), "l"(c));
    return d;
}
__device__ __forceinline__ u64 pack2(float lo, float hi) {
    u64 r;
    asm("mov.b64 %0, {%1, %2};" : "=l"(r) : "f"(lo), "f"(hi));
    return r;
}
__device__ __forceinline__ float2 unpack2(u64 v) {
    float2 f;
    asm("mov.b64 {%0, %1}, %2;" : "=f"(f.x), "=f"(f.y) : "l"(v));
    return f;
}
__device__ __forceinline__ float sigmoid_fast(float v) {
    float e = __expf(-v);
    return __fdividef(1.0f, 1.0f + e);
}
__device__ __forceinline__ float tanh_fast(float v) {
    float a = fabsf(v);
    float e = __expf(-2.0f * a);
    float t = __fdividef(1.0f - e, 1.0f + e);
    return copysignf(t, v);
}
__device__ __forceinline__ void cpasync16(unsigned dst, const float* src) {
    size_t s = __cvta_generic_to_global(src);
    asm volatile("cp.async.cg.shared.global [%0], [%1], 16;" :: "r"(dst), "l"(s) : "memory");
}

// ───────────────────────── Kernel A: gx precompute ─────────────────────────
__global__ void __launch_bounds__(128, 3) gru_gx_kernel(
        const float* __restrict__ x,
        const float* __restrict__ W_ih,
        const float* __restrict__ b_ih,
        const float* __restrict__ b_hh) {
    __shared__ __align__(16) float xsm[WPB][2][ACHUNK * GRU_H];

    const int w = threadIdx.x >> 5;
    const int j = threadIdx.x & 31;
    const int b = blockIdx.x * WPB + w;

    const float* xb = x + (size_t)b * (GRU_T * GRU_H);
    float* gxb = d_gx + (size_t)b * (GRU_T * 96);

    u64 wir[16], wiz[16], win[16];
    {
        const u64* a = (const u64*)(W_ih + (size_t)j * 32);
        const u64* c = (const u64*)(W_ih + (size_t)(32 + j) * 32);
        const u64* d = (const u64*)(W_ih + (size_t)(64 + j) * 32);
#pragma unroll
        for (int k = 0; k < 16; k++) { wir[k] = a[k]; wiz[k] = c[k]; win[k] = d[k]; }
    }
    // Fold b_hh for r,z here (h-independent); n's hidden bias stays in kernel B.
    const u64 ar0 = pack2(b_ih[j] + b_hh[j], 0.0f);
    const u64 az0 = pack2(b_ih[32 + j] + b_hh[32 + j], 0.0f);
    const u64 an0 = pack2(b_ih[64 + j], 0.0f);

    const unsigned sm0 = (unsigned)__cvta_generic_to_shared(&xsm[w][0][0]);
    const unsigned sm1 = (unsigned)__cvta_generic_to_shared(&xsm[w][1][0]);

#pragma unroll
    for (int i = 0; i < 4; i++) cpasync16(sm0 + i * 512 + j * 16, xb + i * 128 + j * 4);
    asm volatile("cp.async.commit_group;" ::: "memory");
#pragma unroll
    for (int i = 0; i < 4; i++)
        cpasync16(sm1 + i * 512 + j * 16, xb + ACHUNK * GRU_H + i * 128 + j * 4);
    asm volatile("cp.async.commit_group;" ::: "memory");

#pragma unroll 1
    for (int c = 0; c < ANCH; c++) {
        asm volatile("cp.async.wait_group 1;" ::: "memory");
        __syncwarp();
        const ulonglong2* xs = (const ulonglong2*)&xsm[w][c & 1][0];

#pragma unroll 2
        for (int tl = 0; tl < ACHUNK; tl++) {
            const ulonglong2* xq = xs + tl * 8;
            u64 ar = ar0, az = az0, an = an0;
#pragma unroll
            for (int q = 0; q < 8; q++) {
                ulonglong2 xx = xq[q];  // uniform broadcast LDS.128
                ar = ffma2(xx.x, wir[2 * q], ar);
                az = ffma2(xx.x, wiz[2 * q], az);
                an = ffma2(xx.x, win[2 * q], an);
                ar = ffma2(xx.y, wir[2 * q + 1], ar);
                az = ffma2(xx.y, wiz[2 * q + 1], az);
                an = ffma2(xx.y, win[2 * q + 1], an);
            }
            float2 fr = unpack2(ar), fz = unpack2(az), fn = unpack2(an);
            float* o = gxb + (size_t)(c * ACHUNK + tl) * 96;
            o[j]      = fr.x + fr.y;
            o[32 + j] = fz.x + fz.y;
            o[64 + j] = fn.x + fn.y;
        }

        __syncwarp();
        if (c + 2 < ANCH) {
            unsigned dst = (c & 1) ? sm1 : sm0;
            const float* src = xb + (size_t)(c + 2) * ACHUNK * GRU_H;
#pragma unroll
            for (int i = 0; i < 4; i++) cpasync16(dst + i * 512 + j * 16, src + i * 128 + j * 4);
        }
        asm volatile("cp.async.commit_group;" ::: "memory");
    }
}

// ──────────────── Kernel B: recurrence, 2 rows per warp ────────────────
__global__ void __launch_bounds__(128, 3) gru_rec_kernel(
        const float* __restrict__ W_hh,
        const float* __restrict__ b_hh,
        const float* __restrict__ w_head,
        const float* __restrict__ b_head,
        float* __restrict__ out) {
    // gx buffers: [warp][buf][row*BCHUNK*96]  (2 rows, 4 steps) = 24 KB
    __shared__ __align__(16) float gxsm[WPB][2][2 * BCHUNK * 96];
    __shared__ __align__(16) float hbuf[WPB][2][2][GRU_H];  // [warp][buf][row][j]

    const int w = threadIdx.x >> 5;
    const int j = threadIdx.x & 31;
    const int g = blockIdx.x * WPB + w;         // global warp id; owns rows 2g, 2g+1

    const float* gx0 = d_gx + (size_t)(2 * g) * (GRU_T * 96);
    const float* gx1 = d_gx + (size_t)(2 * g + 1) * (GRU_T * 96);

    // W_hh rows j, 32+j, 64+j packed (96 regs) — shared by both rows.
    u64 whr[16], whz[16], whn[16];
    {
        const u64* a = (const u64*)(W_hh + (size_t)j * 32);
        const u64* c = (const u64*)(W_hh + (size_t)(32 + j) * 32);
        const u64* d = (const u64*)(W_hh + (size_t)(64 + j) * 32);
#pragma unroll
        for (int k = 0; k < 16; k++) { whr[k] = a[k]; whz[k] = c[k]; whn[k] = d[k]; }
    }
    const u64 anh0 = pack2(b_hh[64 + j], 0.0f);
    const u64 zero2 = pack2(0.0f, 0.0f);

    const unsigned gbase = (unsigned)__cvta_generic_to_shared(&gxsm[w][0][0]);
    const unsigned BUFB = 2 * BCHUNK * 96 * 4;   // 3072 B per buffer

    hbuf[w][0][0][j] = 0.0f;
    hbuf[w][0][1][j] = 0.0f;
    float h0 = 0.0f, h1 = 0.0f;

    // Prefetch gx chunks 0,1. Per buffer: 2 rows × 1536 B; lane copies 3×16B per row.
#pragma unroll
    for (int i = 0; i < 3; i++) {
        cpasync16(gbase + i * 512 + j * 16, gx0 + i * 128 + j * 4);
        cpasync16(gbase + 1536 + i * 512 + j * 16, gx1 + i * 128 + j * 4);
    }
    asm volatile("cp.async.commit_group;" ::: "memory");
#pragma unroll
    for (int i = 0; i < 3; i++) {
        cpasync16(gbase + BUFB + i * 512 + j * 16, gx0 + BCHUNK * 96 + i * 128 + j * 4);
        cpasync16(gbase + BUFB + 1536 + i * 512 + j * 16, gx1 + BCHUNK * 96 + i * 128 + j * 4);
    }
    asm volatile("cp.async.commit_group;" ::: "memory");
    __syncwarp();

#pragma unroll 1
    for (int c = 0; c < BNCH; c++) {
        asm volatile("cp.async.wait_group 1;" ::: "memory");
        __syncwarp();
        const float* gs = &gxsm[w][c & 1][0];

#pragma unroll
        for (int tl = 0; tl < BCHUNK; tl++) {
            const int t = c * BCHUNK + tl;
            const ulonglong2* hq0 = (const ulonglong2*)&hbuf[w][t & 1][0][0];
            const ulonglong2* hq1 = (const ulonglong2*)&hbuf[w][t & 1][1][0];

            u64 ar0 = zero2, az0 = zero2, an0 = anh0;
            u64 ar1 = zero2, az1 = zero2, an1 = anh0;
#pragma unroll
            for (int q = 0; q < 8; q++) {
                ulonglong2 ha = hq0[q];   // row0 h pairs (uniform LDS.128)
                ulonglong2 hb = hq1[q];   // row1 h pairs
                ar0 = ffma2(ha.x, whr[2 * q], ar0);
                az0 = ffma2(ha.x, whz[2 * q], az0);
                an0 = ffma2(ha.x, whn[2 * q], an0);
                ar1 = ffma2(hb.x, whr[2 * q], ar1);
                az1 = ffma2(hb.x, whz[2 * q], az1);
                an1 = ffma2(hb.x, whn[2 * q], an1);
                ar0 = ffma2(ha.y, whr[2 * q + 1], ar0);
                az0 = ffma2(ha.y, whz[2 * q + 1], az0);
                an0 = ffma2(ha.y, whn[2 * q + 1], an0);
                ar1 = ffma2(hb.y, whr[2 * q + 1], ar1);
                az1 = ffma2(hb.y, whz[2 * q + 1], az1);
                an1 = ffma2(hb.y, whn[2 * q + 1], an1);
            }
            // gx reads (smem): row0 at tl*96, row1 at BCHUNK*96 + tl*96
            float gxr0 = gs[tl * 96 + j];
            float gxz0 = gs[tl * 96 + 32 + j];
            float gxn0 = gs[tl * 96 + 64 + j];
            float gxr1 = gs[BCHUNK * 96 + tl * 96 + j];
            float gxz1 = gs[BCHUNK * 96 + tl * 96 + 32 + j];
            float gxn1 = gs[BCHUNK * 96 + tl * 96 + 64 + j];

            float2 fr0 = unpack2(ar0), fz0 = unpack2(az0), fn0 = unpack2(an0);
            float2 fr1 = unpack2(ar1), fz1 = unpack2(az1), fn1 = unpack2(an1);
            float r0 = sigmoid_fast(gxr0 + fr0.x + fr0.y);
            float r1 = sigmoid_fast(gxr1 + fr1.x + fr1.y);
            float z0 = sigmoid_fast(gxz0 + fz0.x + fz0.y);
            float z1 = sigmoid_fast(gxz1 + fz1.x + fz1.y);
            float n0 = tanh_fast(fmaf(r0, fn0.x + fn0.y, gxn0));
            float n1 = tanh_fast(fmaf(r1, fn1.x + fn1.y, gxn1));
            h0 = fmaf(z0, h0 - n0, n0);
            h1 = fmaf(z1, h1 - n1, n1);

            hbuf[w][(t + 1) & 1][0][j] = h0;
            hbuf[w][(t + 1) & 1][1][j] = h1;
            __syncwarp();
        }

        if (c + 2 < BNCH) {
            unsigned dst = gbase + ((c & 1) ? BUFB : 0u);
            const float* s0 = gx0 + (size_t)(c + 2) * BCHUNK * 96;
            const float* s1 = gx1 + (size_t)(c + 2) * BCHUNK * 96;
#pragma unroll
            for (int i = 0; i < 3; i++) {
                cpasync16(dst + i * 512 + j * 16, s0 + i * 128 + j * 4);
                cpasync16(dst + 1536 + i * 512 + j * 16, s1 + i * 128 + j * 4);
            }
        }
        asm volatile("cp.async.commit_group;" ::: "memory");
    }

    // Head for both rows.
    float v0 = h0 * w_head[j];
    float v1 = h1 * w_head[j];
#pragma unroll
    for (int off = 16; off > 0; off >>= 1) {
        v0 += __shfl_xor_sync(FULL, v0, off);
        v1 += __shfl_xor_sync(FULL, v1, off);
    }
    if (j == 0) {
        out[2 * g]     = v0 + b_head[0];
        out[2 * g + 1] = v1 + b_head[0];
    }
}

extern "C" void kernel_launch(void* const* d_in, const int* in_sizes, int n_in,
                              void* d_out, int out_size) {
    const float* x      = (const float*)d_in[0];
    const float* W_ih   = (const float*)d_in[1];
    const float* W_hh   = (const float*)d_in[2];
    const float* b_ih   = (const float*)d_in[3];
    const float* b_hh   = (const float*)d_in[4];
    const float* w_head = (const float*)d_in[5];
    const float* b_head = (const float*)d_in[6];
    float* out = (float*)d_out;

    gru_gx_kernel<<<GRU_B / WPB, 32 * WPB>>>(x, W_ih, b_ih, b_hh);
    gru_rec_kernel<<<GRU_B / (2 * WPB), 32 * WPB>>>(W_hh, b_hh, w_head, b_head, out);
}

// round 9
// speedup vs baseline: 2.5702x; 1.1029x over previous
#include <cuda_runtime.h>
#include <cuda_bf16.h>
#include <cstdint>

// GRU B=4096, T=512, I=H=32.
//  Kernel A (HMMA): gx[r,96] = x[r,32]·W_ih^T + bias via mma.sync bf16 with
//    3-term hi/lo split (fp32-grade), fp32 accumulation. (tcgen05 is gated off
//    by the harness's compute_103 PTX target; mma.sync is baseline PTX.)
//  Kernel B (SIMT): h recurrence at the fp32 FMA roofline (unchanged).

#define GRU_B 4096
#define GRU_T 512
#define GRU_H 32
#define WPB 4
#define BCHUNK 4
#define BNCH (GRU_T / BCHUNK)
#define FULL 0xffffffffu

#define NROWS (GRU_B * GRU_T)        // 2,097,152 flattened (b,t) rows
#define AT_ROWS 64                   // rows per CTA-iter (4 warps × m16)
#define NT64 (NROWS / AT_ROWS)       // 32768 tiles
#define TPC 16                       // tiles per CTA
#define GRID_A (NT64 / TPC)          // 2048 CTAs

typedef unsigned long long u64;

// gx scratch: [B][T][96] fp32 = 805 MB (static device array; no runtime alloc).
__device__ float d_gx[(size_t)GRU_B * GRU_T * 96];

// ───────── common helpers ─────────
__device__ __forceinline__ u64 ffma2(u64 a, u64 b, u64 c) {
    u64 d;
    asm("fma.rn.f32x2 %0, %1, %2, %3;" : "=l"(d) : "l"(a), "l"(b), "l"(c));
    return d;
}
__device__ __forceinline__ u64 pack2(float lo, float hi) {
    u64 r;
    asm("mov.b64 %0, {%1, %2};" : "=l"(r) : "f"(lo), "f"(hi));
    return r;
}
__device__ __forceinline__ float2 unpack2(u64 v) {
    float2 f;
    asm("mov.b64 {%0, %1}, %2;" : "=f"(f.x), "=f"(f.y) : "l"(v));
    return f;
}
__device__ __forceinline__ float sigmoid_fast(float v) {
    float e = __expf(-v);
    return __fdividef(1.0f, 1.0f + e);
}
__device__ __forceinline__ float tanh_fast(float v) {
    float a = fabsf(v);
    float e = __expf(-2.0f * a);
    float t = __fdividef(1.0f - e, 1.0f + e);
    return copysignf(t, v);
}
__device__ __forceinline__ void cpasync16(unsigned dst, const float* src) {
    size_t s = __cvta_generic_to_global(src);
    asm volatile("cp.async.cg.shared.global [%0], [%1], 16;" :: "r"(dst), "l"(s) : "memory");
}
__device__ __forceinline__ uint32_t smem_u32(const void* p) {
    uint32_t a;
    asm("{ .reg .u64 t; cvta.to.shared.u64 t, %1; cvt.u32.u64 %0, t; }" : "=r"(a) : "l"(p));
    return a;
}

// ───────── mma.sync / ldmatrix helpers (baseline PTX, sm_80+) ─────────
__device__ __forceinline__ void ldsm_x4(uint32_t a[4], uint32_t addr) {
    asm volatile("ldmatrix.sync.aligned.m8n8.x4.shared.b16 {%0,%1,%2,%3}, [%4];"
                 : "=r"(a[0]), "=r"(a[1]), "=r"(a[2]), "=r"(a[3]) : "r"(addr));
}
__device__ __forceinline__ void ldsm_x2(uint32_t b[2], uint32_t addr) {
    asm volatile("ldmatrix.sync.aligned.m8n8.x2.shared.b16 {%0,%1}, [%2];"
                 : "=r"(b[0]), "=r"(b[1]) : "r"(addr));
}
__device__ __forceinline__ void mma16816(float c[4], const uint32_t a[4], const uint32_t b[2]) {
    asm volatile(
        "mma.sync.aligned.m16n8k16.row.col.f32.bf16.bf16.f32 "
        "{%0,%1,%2,%3}, {%4,%5,%6,%7}, {%8,%9}, {%0,%1,%2,%3};"
        : "+f"(c[0]), "+f"(c[1]), "+f"(c[2]), "+f"(c[3])
        : "r"(a[0]), "r"(a[1]), "r"(a[2]), "r"(a[3]), "r"(b[0]), "r"(b[1]));
}

// ───────── Kernel A: HMMA gx ─────────
// smem: W hi/lo bf16 [96 rows × 80B stride] + per-warp x staging (double buffer,
// hi/lo, 16 rows × 80B) + bias. 80B row stride → conflict-free ldmatrix.
#define XROWB 80

__global__ void __launch_bounds__(128) gru_gx_mma_kernel(
        const float* __restrict__ x,
        const float* __restrict__ W_ih,
        const float* __restrict__ b_ih,
        const float* __restrict__ b_hh) {
    __shared__ __align__(16) uint8_t wsm[2][96 * XROWB];          // hi, lo
    __shared__ __align__(16) uint8_t xsm[4][2][2][16 * XROWB];    // [warp][buf][hi/lo]
    __shared__ float biassm[96];

    const int tid = threadIdx.x;
    const int wid = tid >> 5;
    const int lane = tid & 31;

    // W_ih [96×32] → hi/lo bf16 into smem (k-contiguous rows, 80B stride).
    for (int i = tid; i < 96 * 32; i += 128) {
        int r = i >> 5, c = i & 31;
        float v = W_ih[i];
        __nv_bfloat16 hi = __float2bfloat16(v);
        __nv_bfloat16 lo = __float2bfloat16(v - __bfloat162float(hi));
        *(__nv_bfloat16*)(&wsm[0][r * XROWB + c * 2]) = hi;
        *(__nv_bfloat16*)(&wsm[1][r * XROWB + c * 2]) = lo;
    }
    if (tid < 96) biassm[tid] = b_ih[tid] + (tid < 64 ? b_hh[tid] : 0.0f);
    __syncthreads();

    // W fragments (held in registers for the whole CTA lifetime).
    // B frag for [n][k] k-contiguous smem: plain ldmatrix (non-trans), n-row addrs.
    uint32_t bh[12][2][2], bl[12][2][2];
    {
        const uint32_t wb0 = smem_u32(&wsm[0][0]);
        const uint32_t wb1 = smem_u32(&wsm[1][0]);
        const int m = lane & 15;
        const uint32_t roff = (uint32_t)((m & 7) * XROWB + ((m >> 3) & 1) * 16);
#pragma unroll
        for (int nt = 0; nt < 12; nt++) {
#pragma unroll
            for (int ks = 0; ks < 2; ks++) {
                uint32_t off = (uint32_t)(nt * 8 * XROWB) + roff + ks * 32;
                ldsm_x2(bh[nt][ks], wb0 + off);
                ldsm_x2(bl[nt][ks], wb1 + off);
            }
        }
    }

    // Per-thread constant addressing.
    const int g = lane >> 3;
    const uint32_t a_roff = (uint32_t)(((g & 1) * 8 + (lane & 7)) * XROWB + (g >> 1) * 16);
    const uint32_t xb_hi[2] = { smem_u32(&xsm[wid][0][0][0]), smem_u32(&xsm[wid][1][0][0]) };
    const uint32_t xb_lo[2] = { smem_u32(&xsm[wid][0][1][0]), smem_u32(&xsm[wid][1][1][0]) };
    const uint32_t sts_off = (uint32_t)((lane >> 1) * XROWB + (lane & 1) * 32);

    const int tile0 = blockIdx.x * TPC;
    float4 xv[4];

    // x loader: 16 rows × 32 fp32 per warp; thread covers row lane/2, half lane&1.
    auto load_x = [&](int it) {
        size_t row = (size_t)(tile0 + it) * AT_ROWS + wid * 16 + (lane >> 1);
        const float4* p = (const float4*)(x + row * 32 + (lane & 1) * 16);
#pragma unroll
        for (int q = 0; q < 4; q++) xv[q] = p[q];
    };
    // hi/lo split + STS into buffer b.
    auto cvt_sts = [&](int b) {
        uint32_t hu[8], lu[8];
#pragma unroll
        for (int q = 0; q < 4; q++) {
            float4 v = xv[q];
            __nv_bfloat162 h0 = __floats2bfloat162_rn(v.x, v.y);
            __nv_bfloat162 h1 = __floats2bfloat162_rn(v.z, v.w);
            float lx = v.x - __bfloat162float(h0.x);
            float ly = v.y - __bfloat162float(h0.y);
            float lz = v.z - __bfloat162float(h1.x);
            float lw = v.w - __bfloat162float(h1.y);
            __nv_bfloat162 l0 = __floats2bfloat162_rn(lx, ly);
            __nv_bfloat162 l1 = __floats2bfloat162_rn(lz, lw);
            hu[2 * q]     = *(uint32_t*)&h0;
            hu[2 * q + 1] = *(uint32_t*)&h1;
            lu[2 * q]     = *(uint32_t*)&l0;
            lu[2 * q + 1] = *(uint32_t*)&l1;
        }
        uint4* dh = (uint4*)(&xsm[wid][b][0][sts_off]);
        uint4* dl = (uint4*)(&xsm[wid][b][1][sts_off]);
        dh[0] = make_uint4(hu[0], hu[1], hu[2], hu[3]);
        dh[1] = make_uint4(hu[4], hu[5], hu[6], hu[7]);
        dl[0] = make_uint4(lu[0], lu[1], lu[2], lu[3]);
        dl[1] = make_uint4(lu[4], lu[5], lu[6], lu[7]);
    };

    // Pipeline prologue.
    load_x(0);
    cvt_sts(0);
    load_x(1);
    __syncwarp();

#pragma unroll 1
    for (int it = 0; it < TPC; it++) {
        const int buf = it & 1;

        // A fragments for this iter (hi, lo × 2 k-steps).
        uint32_t ah[2][4], al[2][4];
#pragma unroll
        for (int ks = 0; ks < 2; ks++) {
            ldsm_x4(ah[ks], xb_hi[buf] + a_roff + ks * 32);
            ldsm_x4(al[ks], xb_lo[buf] + a_roff + ks * 32);
        }
        __syncwarp();  // all lanes done reading buf^1 (prev iter) & this buf

        if (it + 1 < TPC) cvt_sts(buf ^ 1);   // stage next iter
        if (it + 2 < TPC) load_x(it + 2);     // LDG in flight under mma

        // C init = bias (row-independent, per column pair).
        float c[12][4];
#pragma unroll
        for (int nt = 0; nt < 12; nt++) {
            float2 b2 = *(const float2*)(biassm + nt * 8 + (lane & 3) * 2);
            c[nt][0] = b2.x; c[nt][1] = b2.y; c[nt][2] = b2.x; c[nt][3] = b2.y;
        }
        // 3-term split: xhi·Whi + xhi·Wlo + xlo·Whi (fp32 accum).
#pragma unroll
        for (int nt = 0; nt < 12; nt++) {
            mma16816(c[nt], ah[0], bh[nt][0]);
            mma16816(c[nt], ah[1], bh[nt][1]);
            mma16816(c[nt], ah[0], bl[nt][0]);
            mma16816(c[nt], ah[1], bl[nt][1]);
            mma16816(c[nt], al[0], bh[nt][0]);
            mma16816(c[nt], al[1], bh[nt][1]);
        }

        // Epilogue: thread owns rows (lane/4, lane/4+8), cols nt*8+(lane%4)*2.
        {
            size_t grow = (size_t)(tile0 + it) * AT_ROWS + wid * 16 + (lane >> 2);
            float* og = d_gx + grow * 96 + (lane & 3) * 2;
#pragma unroll
            for (int nt = 0; nt < 12; nt++) {
                *(float2*)(og + nt * 8) = make_float2(c[nt][0], c[nt][1]);
                *(float2*)(og + nt * 8 + 8 * 96) = make_float2(c[nt][2], c[nt][3]);
            }
        }
        __syncwarp();  // STS(buf^1) complete before next iter's ldmatrix
    }
}

// ──────────────── Kernel B: recurrence, 2 rows per warp (unchanged) ────────────────
__global__ void __launch_bounds__(128, 3) gru_rec_kernel(
        const float* __restrict__ W_hh,
        const float* __restrict__ b_hh,
        const float* __restrict__ w_head,
        const float* __restrict__ b_head,
        float* __restrict__ out) {
    __shared__ __align__(16) float gxsm[WPB][2][2 * BCHUNK * 96];
    __shared__ __align__(16) float hbuf[WPB][2][2][GRU_H];

    const int w = threadIdx.x >> 5;
    const int j = threadIdx.x & 31;
    const int g = blockIdx.x * WPB + w;

    const float* gx0 = d_gx + (size_t)(2 * g) * (GRU_T * 96);
    const float* gx1 = d_gx + (size_t)(2 * g + 1) * (GRU_T * 96);

    u64 whr[16], whz[16], whn[16];
    {
        const u64* a = (const u64*)(W_hh + (size_t)j * 32);
        const u64* c = (const u64*)(W_hh + (size_t)(32 + j) * 32);
        const u64* d = (const u64*)(W_hh + (size_t)(64 + j) * 32);
#pragma unroll
        for (int k = 0; k < 16; k++) { whr[k] = a[k]; whz[k] = c[k]; whn[k] = d[k]; }
    }
    const u64 anh0 = pack2(b_hh[64 + j], 0.0f);
    const u64 zero2 = pack2(0.0f, 0.0f);

    const unsigned gbase = (unsigned)__cvta_generic_to_shared(&gxsm[w][0][0]);
    const unsigned BUFB = 2 * BCHUNK * 96 * 4;

    hbuf[w][0][0][j] = 0.0f;
    hbuf[w][0][1][j] = 0.0f;
    float h0 = 0.0f, h1 = 0.0f;

#pragma unroll
    for (int i = 0; i < 3; i++) {
        cpasync16(gbase + i * 512 + j * 16, gx0 + i * 128 + j * 4);
        cpasync16(gbase + 1536 + i * 512 + j * 16, gx1 + i * 128 + j * 4);
    }
    asm volatile("cp.async.commit_group;" ::: "memory");
#pragma unroll
    for (int i = 0; i < 3; i++) {
        cpasync16(gbase + BUFB + i * 512 + j * 16, gx0 + BCHUNK * 96 + i * 128 + j * 4);
        cpasync16(gbase + BUFB + 1536 + i * 512 + j * 16, gx1 + BCHUNK * 96 + i * 128 + j * 4);
    }
    asm volatile("cp.async.commit_group;" ::: "memory");
    __syncwarp();

#pragma unroll 1
    for (int c = 0; c < BNCH; c++) {
        asm volatile("cp.async.wait_group 1;" ::: "memory");
        __syncwarp();
        const float* gs = &gxsm[w][c & 1][0];

#pragma unroll
        for (int tl = 0; tl < BCHUNK; tl++) {
            const int t = c * BCHUNK + tl;
            const ulonglong2* hq0 = (const ulonglong2*)&hbuf[w][t & 1][0][0];
            const ulonglong2* hq1 = (const ulonglong2*)&hbuf[w][t & 1][1][0];

            u64 ar0 = zero2, az0 = zero2, an0 = anh0;
            u64 ar1 = zero2, az1 = zero2, an1 = anh0;
#pragma unroll
            for (int q = 0; q < 8; q++) {
                ulonglong2 ha = hq0[q];
                ulonglong2 hb = hq1[q];
                ar0 = ffma2(ha.x, whr[2 * q], ar0);
                az0 = ffma2(ha.x, whz[2 * q], az0);
                an0 = ffma2(ha.x, whn[2 * q], an0);
                ar1 = ffma2(hb.x, whr[2 * q], ar1);
                az1 = ffma2(hb.x, whz[2 * q], az1);
                an1 = ffma2(hb.x, whn[2 * q], an1);
                ar0 = ffma2(ha.y, whr[2 * q + 1], ar0);
                az0 = ffma2(ha.y, whz[2 * q + 1], az0);
                an0 = ffma2(ha.y, whn[2 * q + 1], an0);
                ar1 = ffma2(hb.y, whr[2 * q + 1], ar1);
                az1 = ffma2(hb.y, whz[2 * q + 1], az1);
                an1 = ffma2(hb.y, whn[2 * q + 1], an1);
            }
            float gxr0 = gs[tl * 96 + j];
            float gxz0 = gs[tl * 96 + 32 + j];
            float gxn0 = gs[tl * 96 + 64 + j];
            float gxr1 = gs[BCHUNK * 96 + tl * 96 + j];
            float gxz1 = gs[BCHUNK * 96 + tl * 96 + 32 + j];
            float gxn1 = gs[BCHUNK * 96 + tl * 96 + 64 + j];

            float2 fr0 = unpack2(ar0), fz0 = unpack2(az0), fn0 = unpack2(an0);
            float2 fr1 = unpack2(ar1), fz1 = unpack2(az1), fn1 = unpack2(an1);
            float r0 = sigmoid_fast(gxr0 + fr0.x + fr0.y);
            float r1 = sigmoid_fast(gxr1 + fr1.x + fr1.y);
            float z0 = sigmoid_fast(gxz0 + fz0.x + fz0.y);
            float z1 = sigmoid_fast(gxz1 + fz1.x + fz1.y);
            float n0 = tanh_fast(fmaf(r0, fn0.x + fn0.y, gxn0));
            float n1 = tanh_fast(fmaf(r1, fn1.x + fn1.y, gxn1));
            h0 = fmaf(z0, h0 - n0, n0);
            h1 = fmaf(z1, h1 - n1, n1);

            hbuf[w][(t + 1) & 1][0][j] = h0;
            hbuf[w][(t + 1) & 1][1][j] = h1;
            __syncwarp();
        }

        if (c + 2 < BNCH) {
            unsigned dst = gbase + ((c & 1) ? BUFB : 0u);
            const float* s0 = gx0 + (size_t)(c + 2) * BCHUNK * 96;
            const float* s1 = gx1 + (size_t)(c + 2) * BCHUNK * 96;
#pragma unroll
            for (int i = 0; i < 3; i++) {
                cpasync16(dst + i * 512 + j * 16, s0 + i * 128 + j * 4);
                cpasync16(dst + 1536 + i * 512 + j * 16, s1 + i * 128 + j * 4);
            }
        }
        asm volatile("cp.async.commit_group;" ::: "memory");
    }

    float v0 = h0 * w_head[j];
    float v1 = h1 * w_head[j];
#pragma unroll
    for (int off = 16; off > 0; off >>= 1) {
        v0 += __shfl_xor_sync(FULL, v0, off);
        v1 += __shfl_xor_sync(FULL, v1, off);
    }
    if (j == 0) {
        out[2 * g]     = v0 + b_head[0];
        out[2 * g + 1] = v1 + b_head[0];
    }
}

extern "C" void kernel_launch(void* const* d_in, const int* in_sizes, int n_in,
                              void* d_out, int out_size) {
    const float* x      = (const float*)d_in[0];
    const float* W_ih   = (const float*)d_in[1];
    const float* W_hh   = (const float*)d_in[2];
    const float* b_ih   = (const float*)d_in[3];
    const float* b_hh   = (const float*)d_in[4];
    const float* w_head = (const float*)d_in[5];
    const float* b_head = (const float*)d_in[6];
    float* out = (float*)d_out;

    gru_gx_mma_kernel<<<GRID_A, 128>>>(x, W_ih, b_ih, b_hh);
    gru_rec_kernel<<<GRU_B / (2 * WPB), 32 * WPB>>>(W_hh, b_hh, w_head, b_head, out);
}

// round 10
// speedup vs baseline: 2.7140x; 1.0559x over previous
#include <cuda_runtime.h>
#include <cuda_bf16.h>
#include <cstdint>

// GRU B=4096, T=512, I=H=32 — single fused kernel.
// Per warp (2 batch rows): produce gx for the next 8-step chunk via mma.sync
// bf16 3-term hi/lo split (tensor pipe, fp32 accum) into per-warp smem, then run
// the fp32 SIMT recurrence (fma pipe) on it. No gx DRAM traffic, no kernel A.

#define GRU_T 512
#define GRU_B 4096
#define WPB 4
#define CHUNK 8
#define NCH (GRU_T / CHUNK)     // 64
#define FULL 0xffffffffu

typedef unsigned long long u64;

// ── dynamic smem layout (bytes) ──
#define S_WHI   0               // W_ih hi bf16: 96 rows × 80B
#define S_WLO   7680            // W_ih lo
#define S_BIAS  15360           // 96 × f32
#define S_XS    15744           // x fp32 staging: 4 warps × 2 buf × 2048B
#define S_XT    32128           // x bf16 tiles: 4 warps × (hi 1280 + lo 1280)
#define S_GX    42368           // gx: 4 warps × 1536 f32 (6144B)
#define S_TOTAL 66944

// ── helpers ──
__device__ __forceinline__ u64 ffma2(u64 a, u64 b, u64 c) {
    u64 d;
    asm("fma.rn.f32x2 %0, %1, %2, %3;" : "=l"(d) : "l"(a), "l"(b), "l"(c));
    return d;
}
__device__ __forceinline__ u64 pack2(float lo, float hi) {
    u64 r;
    asm("mov.b64 %0, {%1, %2};" : "=l"(r) : "f"(lo), "f"(hi));
    return r;
}
__device__ __forceinline__ float2 unpack2(u64 v) {
    float2 f;
    asm("mov.b64 {%0, %1}, %2;" : "=f"(f.x), "=f"(f.y) : "l"(v));
    return f;
}
__device__ __forceinline__ float sigmoid_fast(float v) {
    float e = __expf(-v);
    return __fdividef(1.0f, 1.0f + e);
}
__device__ __forceinline__ float tanh_fast(float v) {
    float a = fabsf(v);
    float e = __expf(-2.0f * a);
    float t = __fdividef(1.0f - e, 1.0f + e);
    return copysignf(t, v);
}
__device__ __forceinline__ void cpasync16(uint32_t dst, const float* src) {
    size_t s = __cvta_generic_to_global(src);
    asm volatile("cp.async.cg.shared.global [%0], [%1], 16;" :: "r"(dst), "l"(s) : "memory");
}
__device__ __forceinline__ uint32_t smem_u32(const void* p) {
    uint32_t a;
    asm("{ .reg .u64 t; cvta.to.shared.u64 t, %1; cvt.u32.u64 %0, t; }" : "=r"(a) : "l"(p));
    return a;
}
__device__ __forceinline__ void ldsm_x4(uint32_t a[4], uint32_t addr) {
    asm volatile("ldmatrix.sync.aligned.m8n8.x4.shared.b16 {%0,%1,%2,%3}, [%4];"
                 : "=r"(a[0]), "=r"(a[1]), "=r"(a[2]), "=r"(a[3]) : "r"(addr));
}
__device__ __forceinline__ void ldsm_x2(uint32_t b[2], uint32_t addr) {
    asm volatile("ldmatrix.sync.aligned.m8n8.x2.shared.b16 {%0,%1}, [%2];"
                 : "=r"(b[0]), "=r"(b[1]) : "r"(addr));
}
__device__ __forceinline__ void mma16816(float c[4], const uint32_t a[4], const uint32_t b[2]) {
    asm volatile(
        "mma.sync.aligned.m16n8k16.row.col.f32.bf16.bf16.f32 "
        "{%0,%1,%2,%3}, {%4,%5,%6,%7}, {%8,%9}, {%0,%1,%2,%3};"
        : "+f"(c[0]), "+f"(c[1]), "+f"(c[2]), "+f"(c[3])
        : "r"(a[0]), "r"(a[1]), "r"(a[2]), "r"(a[3]), "r"(b[0]), "r"(b[1]));
}

__global__ void __launch_bounds__(128, 3) gru_fused_kernel(
        const float* __restrict__ x,
        const float* __restrict__ W_ih,
        const float* __restrict__ W_hh,
        const float* __restrict__ b_ih,
        const float* __restrict__ b_hh,
        const float* __restrict__ w_head,
        const float* __restrict__ b_head,
        float* __restrict__ out) {
    extern __shared__ __align__(128) char sm[];
    __shared__ __align__(16) float hbuf[WPB][2][2][32];  // [warp][buf][row][j]

    const int tid = threadIdx.x;
    const int w = tid >> 5;
    const int lane = tid & 31;
    const int g = blockIdx.x * WPB + w;      // warp owns batch rows 2g, 2g+1

    // ── CTA init: W_ih → smem bf16 hi/lo (80B row stride), bias ──
    for (int i = tid; i < 96 * 32; i += 128) {
        int r = i >> 5, c = i & 31;
        float v = W_ih[i];
        __nv_bfloat16 hi = __float2bfloat16(v);
        __nv_bfloat16 lo = __float2bfloat16(v - __bfloat162float(hi));
        *(__nv_bfloat16*)(sm + S_WHI + r * 80 + c * 2) = hi;
        *(__nv_bfloat16*)(sm + S_WLO + r * 80 + c * 2) = lo;
    }
    if (tid < 96)
        *(float*)(sm + S_BIAS + tid * 4) = b_ih[tid] + (tid < 64 ? b_hh[tid] : 0.0f);

    // ── W_hh rows j, 32+j, 64+j packed into registers (consumer workhorse) ──
    u64 whr[16], whz[16], whn[16];
    {
        const u64* a = (const u64*)(W_hh + (size_t)lane * 32);
        const u64* c = (const u64*)(W_hh + (size_t)(32 + lane) * 32);
        const u64* d = (const u64*)(W_hh + (size_t)(64 + lane) * 32);
#pragma unroll
        for (int k = 0; k < 16; k++) { whr[k] = a[k]; whz[k] = c[k]; whn[k] = d[k]; }
    }
    const u64 anh0 = pack2(b_hh[64 + lane], 0.0f);
    const u64 zero2 = pack2(0.0f, 0.0f);
    __syncthreads();

    // ── per-warp smem addresses ──
    const uint32_t smb = smem_u32(sm);
    const uint32_t xsb  = smb + S_XS + w * 4096;            // fp32 x staging (2 bufs)
    const uint32_t xth  = smb + S_XT + w * 2560;            // bf16 x hi tile
    const uint32_t xtl  = xth + 1280;                       // bf16 x lo tile
    float* gxs = (float*)(sm + S_GX + w * 6144);            // gx chunk (16 rows × 96)
    const float* biasf = (const float*)(sm + S_BIAS);

    const float* xr0 = x + (size_t)(2 * g) * GRU_T * 32;
    const float* xr1 = x + (size_t)(2 * g + 1) * GRU_T * 32;

    // frag addressing constants
    const int gq = lane >> 3;
    const uint32_t a_roff = (uint32_t)(((gq & 1) * 8 + (lane & 7)) * 80 + (gq >> 1) * 16);
    const uint32_t sts_off = (uint32_t)((lane >> 1) * 80 + (lane & 1) * 32);
    const int mh = lane & 15;
    const uint32_t w_roff = (uint32_t)((mh & 7) * 80 + ((mh >> 3) & 1) * 16);

    // ── x staging: 2KB per chunk per warp (r0 8 steps = 1KB, r1 = 1KB) ──
    auto stage_x = [&](int cc) {
        uint32_t dst = xsb + (cc & 1) * 2048;
        const float* s0 = xr0 + (size_t)cc * CHUNK * 32;
        const float* s1 = xr1 + (size_t)cc * CHUNK * 32;
        cpasync16(dst + lane * 16, s0 + lane * 4);
        cpasync16(dst + 512 + lane * 16, s0 + 128 + lane * 4);
        cpasync16(dst + 1024 + lane * 16, s1 + lane * 4);
        cpasync16(dst + 1536 + lane * 16, s1 + 128 + lane * 4);
    };
    stage_x(0);
    asm volatile("cp.async.commit_group;" ::: "memory");
    stage_x(1);
    asm volatile("cp.async.commit_group;" ::: "memory");

    hbuf[w][0][0][lane] = 0.0f;
    hbuf[w][0][1][lane] = 0.0f;
    float h0 = 0.0f, h1 = 0.0f;
    __syncwarp();

#pragma unroll 1
    for (int c = 0; c < NCH; c++) {
        // ── produce gx chunk c (tensor pipe) ──
        asm volatile("cp.async.wait_group 1;" ::: "memory");
        __syncwarp();

        // fp32 x → hi/lo bf16 tiles. Lane covers tile row lane/2, half lane&1.
        {
            const float4* xp = (const float4*)(sm + (xsb - smb) + (c & 1) * 2048
                                               + (lane >> 1) * 128 + (lane & 1) * 64);
            uint32_t hu[8], lu[8];
#pragma unroll
            for (int q = 0; q < 4; q++) {
                float4 v = xp[q];
                __nv_bfloat162 hA = __floats2bfloat162_rn(v.x, v.y);
                __nv_bfloat162 hB = __floats2bfloat162_rn(v.z, v.w);
                __nv_bfloat162 lA = __floats2bfloat162_rn(v.x - __bfloat162float(hA.x),
                                                          v.y - __bfloat162float(hA.y));
                __nv_bfloat162 lB = __floats2bfloat162_rn(v.z - __bfloat162float(hB.x),
                                                          v.w - __bfloat162float(hB.y));
                hu[2 * q]     = *(uint32_t*)&hA;
                hu[2 * q + 1] = *(uint32_t*)&hB;
                lu[2 * q]     = *(uint32_t*)&lA;
                lu[2 * q + 1] = *(uint32_t*)&lB;
            }
            uint4* dh = (uint4*)(sm + (xth - smb) + sts_off);
            uint4* dl = (uint4*)(sm + (xtl - smb) + sts_off);
            dh[0] = make_uint4(hu[0], hu[1], hu[2], hu[3]);
            dh[1] = make_uint4(hu[4], hu[5], hu[6], hu[7]);
            dl[0] = make_uint4(lu[0], lu[1], lu[2], lu[3]);
            dl[1] = make_uint4(lu[4], lu[5], lu[6], lu[7]);
        }
        __syncwarp();

        uint32_t ah[2][4], al[2][4];
#pragma unroll
        for (int ks = 0; ks < 2; ks++) {
            ldsm_x4(ah[ks], xth + a_roff + ks * 32);
            ldsm_x4(al[ks], xtl + a_roff + ks * 32);
        }

        // prefetch x for chunk c+2 (overwrites buf c&1 — reads done, syncwarp'd)
        if (c + 2 < NCH) stage_x(c + 2);
        asm volatile("cp.async.commit_group;" ::: "memory");

        // 12 n-tiles × (3-term split × 2 ksteps); C init = bias; STS to gxs.
#pragma unroll
        for (int nt = 0; nt < 12; nt++) {
            uint32_t bh0[2], bh1[2], bl0[2], bl1[2];
            ldsm_x2(bh0, smb + S_WHI + nt * 640 + w_roff);
            ldsm_x2(bh1, smb + S_WHI + nt * 640 + w_roff + 32);
            ldsm_x2(bl0, smb + S_WLO + nt * 640 + w_roff);
            ldsm_x2(bl1, smb + S_WLO + nt * 640 + w_roff + 32);
            float2 b2 = *(const float2*)(biasf + nt * 8 + (lane & 3) * 2);
            float cc[4] = { b2.x, b2.y, b2.x, b2.y };
            mma16816(cc, ah[0], bh0);
            mma16816(cc, ah[1], bh1);
            mma16816(cc, ah[0], bl0);
            mma16816(cc, ah[1], bl1);
            mma16816(cc, al[0], bh0);
            mma16816(cc, al[1], bh1);
            float* o = gxs + (lane >> 2) * 96 + nt * 8 + (lane & 3) * 2;
            *(float2*)o         = make_float2(cc[0], cc[1]);
            *(float2*)(o + 768) = make_float2(cc[2], cc[3]);
        }
        __syncwarp();

        // ── consume: 8 recurrence steps (fma pipe) ──
#pragma unroll
        for (int tl = 0; tl < CHUNK; tl++) {
            const int t = c * CHUNK + tl;
            const ulonglong2* hq0 = (const ulonglong2*)&hbuf[w][t & 1][0][0];
            const ulonglong2* hq1 = (const ulonglong2*)&hbuf[w][t & 1][1][0];

            u64 ar0 = zero2, az0 = zero2, an0 = anh0;
            u64 ar1 = zero2, az1 = zero2, an1 = anh0;
#pragma unroll
            for (int q = 0; q < 8; q++) {
                ulonglong2 ha = hq0[q];
                ulonglong2 hb = hq1[q];
                ar0 = ffma2(ha.x, whr[2 * q], ar0);
                az0 = ffma2(ha.x, whz[2 * q], az0);
                an0 = ffma2(ha.x, whn[2 * q], an0);
                ar1 = ffma2(hb.x, whr[2 * q], ar1);
                az1 = ffma2(hb.x, whz[2 * q], az1);
                an1 = ffma2(hb.x, whn[2 * q], an1);
                ar0 = ffma2(ha.y, whr[2 * q + 1], ar0);
                az0 = ffma2(ha.y, whz[2 * q + 1], az0);
                an0 = ffma2(ha.y, whn[2 * q + 1], an0);
                ar1 = ffma2(hb.y, whr[2 * q + 1], ar1);
                az1 = ffma2(hb.y, whz[2 * q + 1], az1);
                an1 = ffma2(hb.y, whn[2 * q + 1], an1);
            }
            float gxr0 = gxs[tl * 96 + lane];
            float gxz0 = gxs[tl * 96 + 32 + lane];
            float gxn0 = gxs[tl * 96 + 64 + lane];
            float gxr1 = gxs[768 + tl * 96 + lane];
            float gxz1 = gxs[768 + tl * 96 + 32 + lane];
            float gxn1 = gxs[768 + tl * 96 + 64 + lane];

            float2 fr0 = unpack2(ar0), fz0 = unpack2(az0), fn0 = unpack2(an0);
            float2 fr1 = unpack2(ar1), fz1 = unpack2(az1), fn1 = unpack2(an1);
            float r0 = sigmoid_fast(gxr0 + fr0.x + fr0.y);
            float r1 = sigmoid_fast(gxr1 + fr1.x + fr1.y);
            float z0 = sigmoid_fast(gxz0 + fz0.x + fz0.y);
            float z1 = sigmoid_fast(gxz1 + fz1.x + fz1.y);
            float n0 = tanh_fast(fmaf(r0, fn0.x + fn0.y, gxn0));
            float n1 = tanh_fast(fmaf(r1, fn1.x + fn1.y, gxn1));
            h0 = fmaf(z0, h0 - n0, n0);
            h1 = fmaf(z1, h1 - n1, n1);

            hbuf[w][(t + 1) & 1][0][lane] = h0;
            hbuf[w][(t + 1) & 1][1][lane] = h1;
            __syncwarp();
        }
    }

    // ── head ──
    float v0 = h0 * w_head[lane];
    float v1 = h1 * w_head[lane];
#pragma unroll
    for (int off = 16; off > 0; off >>= 1) {
        v0 += __shfl_xor_sync(FULL, v0, off);
        v1 += __shfl_xor_sync(FULL, v1, off);
    }
    if (lane == 0) {
        out[2 * g]     = v0 + b_head[0];
        out[2 * g + 1] = v1 + b_head[0];
    }
}

extern "C" void kernel_launch(void* const* d_in, const int* in_sizes, int n_in,
                              void* d_out, int out_size) {
    const float* x      = (const float*)d_in[0];
    const float* W_ih   = (const float*)d_in[1];
    const float* W_hh   = (const float*)d_in[2];
    const float* b_ih   = (const float*)d_in[3];
    const float* b_hh   = (const float*)d_in[4];
    const float* w_head = (const float*)d_in[5];
    const float* b_head = (const float*)d_in[6];
    float* out = (float*)d_out;

    cudaFuncSetAttribute(gru_fused_kernel,
                         cudaFuncAttributeMaxDynamicSharedMemorySize, S_TOTAL);
    gru_fused_kernel<<<GRU_B / (2 * WPB), 32 * WPB, S_TOTAL>>>(
        x, W_ih, W_hh, b_ih, b_hh, w_head, b_head, out);
}